// round 8
// baseline (speedup 1.0000x reference)
#include <cuda_runtime.h>
#include <math.h>

#define N_NODES 8192
#define P_META 3
#define IN_F 256
#define HIDD 64
#define N_HEADS 8
#define HD 512
#define OUT_F 64
#define NE 262144

// ---------------- scratch (static device allocations; no runtime alloc) ----
__device__ float d_feat[P_META][N_NODES * HD];    // 48 MB
__device__ float d_zp[P_META][N_NODES * HD];      // 48 MB
__device__ float d_el[P_META][N_NODES * N_HEADS];
__device__ float d_er[P_META][N_NODES * N_HEADS];
__device__ float d_invd[P_META][N_NODES * N_HEADS];
__device__ int   d_counts[P_META][N_NODES];
__device__ int   d_cursor[P_META][N_NODES];
__device__ int   d_offsets[P_META][N_NODES + 1];
__device__ int   d_csrsrc[P_META][NE];
__device__ float d_wsum[P_META];
__device__ float d_beta[P_META];
__device__ float d_v[HD];                         // W1 @ W2 collapsed
__device__ float d_c;                             // b1 . W2
__device__ float d_z[N_NODES * HD];               // beta-combined features

// ---------------------------------------------------------------- utilities
__global__ void zero_misc_kernel() {
    int p = blockIdx.y;
    int i = blockIdx.x * blockDim.x + threadIdx.x;
    if (i < N_NODES) d_counts[p][i] = 0;
    if (p == 0 && i < P_META) d_wsum[i] = 0.f;
}

__global__ void zero_atten_kernel(float4* a) {
    int i = blockIdx.x * blockDim.x + threadIdx.x;   // N*N/4 elements
    a[i] = make_float4(0.f, 0.f, 0.f, 0.f);
}

// ------------------------------------------------ feat = h @ fc_p (fp32 GEMM)
__global__ void __launch_bounds__(256, 2)
gemm_feat_kernel(const float* __restrict__ A,    // [8192,256]
                 const float* __restrict__ fc) { // [P,256,512]
    const int p = blockIdx.z;
    const float* __restrict__ B = fc + (size_t)p * IN_F * HD;
    float* __restrict__ C = d_feat[p];
    __shared__ float As[8][128];
    __shared__ float Bs[8][128];
    const int bm = blockIdx.y * 128;
    const int bn = blockIdx.x * 128;
    const int t = threadIdx.x;
    const int ty = t >> 4, tx = t & 15;

    const int arow = t >> 1;
    const int acol = (t & 1) * 4;
    const int brow = t >> 5;
    const int bcol = (t & 31) * 4;

    float acc[8][8];
#pragma unroll
    for (int i = 0; i < 8; i++)
#pragma unroll
        for (int j = 0; j < 8; j++) acc[i][j] = 0.f;

    for (int k0 = 0; k0 < IN_F; k0 += 8) {
        float4 av = *(const float4*)&A[(size_t)(bm + arow) * IN_F + k0 + acol];
        float4 bv = *(const float4*)&B[(size_t)(k0 + brow) * HD + bn + bcol];
        __syncthreads();
        As[acol + 0][arow] = av.x;
        As[acol + 1][arow] = av.y;
        As[acol + 2][arow] = av.z;
        As[acol + 3][arow] = av.w;
        *(float4*)&Bs[brow][bcol] = bv;
        __syncthreads();
#pragma unroll
        for (int k = 0; k < 8; k++) {
            float a[8], b[8];
            *(float4*)&a[0] = *(const float4*)&As[k][ty * 8];
            *(float4*)&a[4] = *(const float4*)&As[k][ty * 8 + 4];
            *(float4*)&b[0] = *(const float4*)&Bs[k][tx * 8];
            *(float4*)&b[4] = *(const float4*)&Bs[k][tx * 8 + 4];
#pragma unroll
            for (int i = 0; i < 8; i++)
#pragma unroll
                for (int j = 0; j < 8; j++) acc[i][j] += a[i] * b[j];
        }
    }
#pragma unroll
    for (int i = 0; i < 8; i++) {
        float* cr = &C[(size_t)(bm + ty * 8 + i) * HD + bn + tx * 8];
        *(float4*)&cr[0] = make_float4(acc[i][0], acc[i][1], acc[i][2], acc[i][3]);
        *(float4*)&cr[4] = make_float4(acc[i][4], acc[i][5], acc[i][6], acc[i][7]);
    }
}

// ------------------------------------------------ el/er per (node, head, p)
__global__ void eler_kernel(const float* __restrict__ al,
                            const float* __restrict__ ar) {
    int p = blockIdx.y;
    int n = blockIdx.x;
    int h = threadIdx.x >> 5;
    int lane = threadIdx.x & 31;
    float2 f = *(const float2*)&d_feat[p][(size_t)n * HD + h * HIDD + lane * 2];
    float2 a = *(const float2*)&al[p * HD + h * HIDD + lane * 2];
    float2 b = *(const float2*)&ar[p * HD + h * HIDD + lane * 2];
    float sl = f.x * a.x + f.y * a.y;
    float sr = f.x * b.x + f.y * b.y;
#pragma unroll
    for (int o = 16; o; o >>= 1) {
        sl += __shfl_xor_sync(0xffffffffu, sl, o);
        sr += __shfl_xor_sync(0xffffffffu, sr, o);
    }
    if (lane == 0) {
        d_el[p][n * N_HEADS + h] = sl;
        d_er[p][n * N_HEADS + h] = sr;
    }
}

// ------------------------------------------------ CSR build by dst
__global__ void hist_kernel(const int* __restrict__ dst) {
    int p = blockIdx.y;
    int e = blockIdx.x * blockDim.x + threadIdx.x;
    if (e < NE) atomicAdd(&d_counts[p][dst[p * NE + e]], 1);
}

__global__ void scan_kernel() {
    int p = blockIdx.x;
    __shared__ int sh[1024];
    int t = threadIdx.x;
    int base = t * 8;
    int loc[8];
    int s = 0;
#pragma unroll
    for (int i = 0; i < 8; i++) { loc[i] = s; s += d_counts[p][base + i]; }
    sh[t] = s;
    __syncthreads();
    for (int ofs = 1; ofs < 1024; ofs <<= 1) {
        int v = (t >= ofs) ? sh[t - ofs] : 0;
        __syncthreads();
        sh[t] += v;
        __syncthreads();
    }
    int pre = (t == 0) ? 0 : sh[t - 1];
#pragma unroll
    for (int i = 0; i < 8; i++) {
        int o = pre + loc[i];
        d_offsets[p][base + i] = o;
        d_cursor[p][base + i] = o;
    }
    if (t == 1023) d_offsets[p][N_NODES] = sh[1023];
}

__global__ void csr_scatter_kernel(const int* __restrict__ src,
                                   const int* __restrict__ dst) {
    int p = blockIdx.y;
    int e = blockIdx.x * blockDim.x + threadIdx.x;
    if (e < NE) {
        int pos = atomicAdd(&d_cursor[p][dst[p * NE + e]], 1);
        d_csrsrc[p][pos] = src[p * NE + e];
    }
}

// ------------------------------------------------ warp-per-dst aggregation
// ONE warp handles ALL 8 heads of one dst node. Lane l owns feature dims
// [16l, 16l+16) => head = l>>2. Per edge: one 32B el-row sector + one
// coalesced 2KB feat row. 8x fewer edge iterations than warp-per-(dst,head).
__global__ void __launch_bounds__(256)
gat_aggregate_kernel(const float* __restrict__ bias) {
    int p = blockIdx.y;
    int w = threadIdx.x >> 5;
    int dn = blockIdx.x * 8 + w;
    int lane = threadIdx.x & 31;
    int head = lane >> 2;
    int dimb = lane * 16;                         // first of 16 dims owned

    int s0 = d_offsets[p][dn], s1 = d_offsets[p][dn + 1];
    float erv = d_er[p][dn * N_HEADS + head];
    const float* __restrict__ el = d_el[p];
    const int* __restrict__ csrc = d_csrsrc[p];
    const float* __restrict__ feat = d_feat[p];

    float acc[16];
#pragma unroll
    for (int j = 0; j < 16; j++) acc[j] = 0.f;
    float ssum = 0.f;

    int i = s0;
    int sA = 0; float elA = 0.f;
    float4 fA0, fA1, fA2, fA3;
    if (i < s1) {
        sA = csrc[i];
        elA = el[sA * N_HEADS + head];
        const float4* fr = (const float4*)&feat[(size_t)sA * HD + dimb];
        fA0 = fr[0]; fA1 = fr[1]; fA2 = fr[2]; fA3 = fr[3];
    }
    while (i < s1) {
        int sB = 0; float elB = 0.f;
        float4 fB0, fB1, fB2, fB3;
        if (i + 1 < s1) {
            sB = csrc[i + 1];
            elB = el[sB * N_HEADS + head];
            const float4* fr = (const float4*)&feat[(size_t)sB * HD + dimb];
            fB0 = fr[0]; fB1 = fr[1]; fB2 = fr[2]; fB3 = fr[3];
        }
        float ev = elA + erv;
        ev = ev > 0.f ? ev : 0.2f * ev;
        float a = __expf(ev);
        ssum += a;
        acc[0]  += a * fA0.x; acc[1]  += a * fA0.y; acc[2]  += a * fA0.z; acc[3]  += a * fA0.w;
        acc[4]  += a * fA1.x; acc[5]  += a * fA1.y; acc[6]  += a * fA1.z; acc[7]  += a * fA1.w;
        acc[8]  += a * fA2.x; acc[9]  += a * fA2.y; acc[10] += a * fA2.z; acc[11] += a * fA2.w;
        acc[12] += a * fA3.x; acc[13] += a * fA3.y; acc[14] += a * fA3.z; acc[15] += a * fA3.w;
        sA = sB; elA = elB;
        fA0 = fB0; fA1 = fB1; fA2 = fB2; fA3 = fB3;
        i++;
    }

    float inv = ssum > 0.f ? 1.f / ssum : 0.f;
    if ((lane & 3) == 0) d_invd[p][dn * N_HEADS + head] = inv;

    const float4* bv = (const float4*)&bias[p * HD + dimb];
    float4 b0 = bv[0], b1 = bv[1], b2 = bv[2], b3 = bv[3];
    float o[16];
    o[0]  = acc[0]  * inv + b0.x; o[1]  = acc[1]  * inv + b0.y;
    o[2]  = acc[2]  * inv + b0.z; o[3]  = acc[3]  * inv + b0.w;
    o[4]  = acc[4]  * inv + b1.x; o[5]  = acc[5]  * inv + b1.y;
    o[6]  = acc[6]  * inv + b1.z; o[7]  = acc[7]  * inv + b1.w;
    o[8]  = acc[8]  * inv + b2.x; o[9]  = acc[9]  * inv + b2.y;
    o[10] = acc[10] * inv + b2.z; o[11] = acc[11] * inv + b2.w;
    o[12] = acc[12] * inv + b3.x; o[13] = acc[13] * inv + b3.y;
    o[14] = acc[14] * inv + b3.z; o[15] = acc[15] * inv + b3.w;
#pragma unroll
    for (int j = 0; j < 16; j++) o[j] = o[j] > 0.f ? o[j] : (__expf(o[j]) - 1.f);

    float4* zr = (float4*)&d_zp[p][(size_t)dn * HD + dimb];
    zr[0] = make_float4(o[0],  o[1],  o[2],  o[3]);
    zr[1] = make_float4(o[4],  o[5],  o[6],  o[7]);
    zr[2] = make_float4(o[8],  o[9],  o[10], o[11]);
    zr[3] = make_float4(o[12], o[13], o[14], o[15]);
}

// ------------------------------------------------ semantic attention
__global__ void sem_v_kernel(const float* __restrict__ w1,
                             const float* __restrict__ w2,
                             const float* __restrict__ b1) {
    int k = threadIdx.x + blockIdx.x * blockDim.x;   // 512
    float s = 0.f;
    for (int j = 0; j < 128; j++) s += w1[k * 128 + j] * w2[j];
    d_v[k] = s;
    if (k == 0) {
        float c = 0.f;
        for (int j = 0; j < 128; j++) c += b1[j] * w2[j];
        d_c = c;
    }
}

__global__ void sem_w_kernel() {
    int gw = (blockIdx.x * blockDim.x + threadIdx.x) >> 5;   // N*P warps
    int lane = threadIdx.x & 31;
    int n = gw / P_META;
    int p = gw - n * P_META;
    if (n >= N_NODES) return;
    const float* z = &d_zp[p][(size_t)n * HD];
    float s = 0.f;
#pragma unroll
    for (int k = lane; k < HD; k += 32) s += z[k] * d_v[k];
#pragma unroll
    for (int o = 16; o; o >>= 1) s += __shfl_xor_sync(0xffffffffu, s, o);
    if (lane == 0) {
        float w = s + d_c;
        w = w > 0.f ? w : 0.01f * w;
        atomicAdd(&d_wsum[p], w);
    }
}

__global__ void beta_kernel() {
    if (threadIdx.x == 0) {
        float w0 = d_wsum[0] / (float)N_NODES;
        float w1 = d_wsum[1] / (float)N_NODES;
        float w2 = d_wsum[2] / (float)N_NODES;
        float mx = fmaxf(w0, fmaxf(w1, w2));
        float e0 = expf(w0 - mx), e1 = expf(w1 - mx), e2 = expf(w2 - mx);
        float s = e0 + e1 + e2;
        d_beta[0] = e0 / s;
        d_beta[1] = e1 / s;
        d_beta[2] = e2 / s;
    }
}

// ------------------------------------------------ z = sum_p beta_p * zp
__global__ void combine_z_kernel() {
    int i = blockIdx.x * blockDim.x + threadIdx.x;   // N*HD/4
    float b0 = d_beta[0], b1 = d_beta[1], b2 = d_beta[2];
    float4 a = ((const float4*)&d_zp[0][0])[i];
    float4 b = ((const float4*)&d_zp[1][0])[i];
    float4 c = ((const float4*)&d_zp[2][0])[i];
    float4 r;
    r.x = b0 * a.x + b1 * b.x + b2 * c.x;
    r.y = b0 * a.y + b1 * b.y + b2 * c.y;
    r.z = b0 * a.z + b1 * b.z + b2 * c.z;
    r.w = b0 * a.w + b1 * b.w + b2 * c.w;
    ((float4*)d_z)[i] = r;
}

// ------------------------------------------------ out = z @ pred_w + pred_b
__global__ void out_kernel(const float* __restrict__ pw,
                           const float* __restrict__ pb,
                           float* __restrict__ out) {
    __shared__ float zs[HD];
    int n = blockIdx.x;
    int t = threadIdx.x;   // 64
    for (int k = t; k < HD; k += 64) zs[k] = d_z[(size_t)n * HD + k];
    __syncthreads();
    float acc = pb[t];
#pragma unroll 8
    for (int k = 0; k < HD; k++) acc += zs[k] * pw[k * OUT_F + t];
    out[(size_t)n * OUT_F + t] = acc;
}

// ------------------------------------------------ atten scatter (fused alpha)
__global__ void atten_scatter_kernel(const int* __restrict__ src,
                                     const int* __restrict__ dst,
                                     float* __restrict__ atten) {
    int p = blockIdx.y;
    int e = blockIdx.x * blockDim.x + threadIdx.x;
    if (e >= NE) return;
    int s = src[p * NE + e];
    int d = dst[p * NE + e];
    const float* elrow = &d_el[p][s * N_HEADS];
    const float* errow = &d_er[p][d * N_HEADS];
    const float* invrow = &d_invd[p][d * N_HEADS];
    float a = 0.f;
#pragma unroll
    for (int h = 0; h < N_HEADS; h++) {
        float ev = elrow[h] + errow[h];
        ev = ev > 0.f ? ev : 0.2f * ev;
        a += __expf(ev) * invrow[h];
    }
    float v = a * 0.125f * d_beta[p];
    atomicAdd(&atten[(size_t)s * N_NODES + d], v);
}

// ---------------------------------------------------------------- launcher
extern "C" void kernel_launch(void* const* d_in, const int* in_sizes, int n_in,
                              void* d_out, int out_size) {
    const float* h    = (const float*)d_in[0];
    const int*   esrc = (const int*)d_in[1];
    const int*   edst = (const int*)d_in[2];
    const float* fc   = (const float*)d_in[3];
    const float* al   = (const float*)d_in[4];
    const float* ar   = (const float*)d_in[5];
    const float* bias = (const float*)d_in[6];
    const float* w1   = (const float*)d_in[7];
    const float* b1   = (const float*)d_in[8];
    const float* w2   = (const float*)d_in[9];
    const float* pw   = (const float*)d_in[10];
    const float* pb   = (const float*)d_in[11];

    const long long SZ_OUT   = (long long)N_NODES * OUT_F;      // 524288
    const long long SZ_ATTEN = (long long)N_NODES * N_NODES;    // 67108864
    long long osz = (long long)out_size;

    float* out_ptr = nullptr;
    float* atten_ptr = nullptr;
    if (osz >= SZ_OUT + SZ_ATTEN) {
        out_ptr = (float*)d_out;                 // [out | atten]
        atten_ptr = out_ptr + SZ_OUT;
    } else if (osz == SZ_OUT) {
        out_ptr = (float*)d_out;
    } else if (osz == SZ_ATTEN) {
        atten_ptr = (float*)d_out;
    } else {
        out_ptr = (float*)d_out;
    }

    // ---- optional second stream for fork/join overlap (static, one-time) ----
    static cudaStream_t s2 = (cudaStream_t)0;
    static cudaEvent_t evFork = nullptr, evJoin = nullptr;
    static int streams_ok = -1;
    if (streams_ok < 0) {
        cudaStream_t ts;
        cudaEvent_t e1, e2;
        if (cudaStreamCreateWithFlags(&ts, cudaStreamNonBlocking) == cudaSuccess &&
            cudaEventCreateWithFlags(&e1, cudaEventDisableTiming) == cudaSuccess &&
            cudaEventCreateWithFlags(&e2, cudaEventDisableTiming) == cudaSuccess) {
            s2 = ts; evFork = e1; evJoin = e2; streams_ok = 1;
        } else {
            streams_ok = 0;
        }
    }
    cudaStream_t side = streams_ok ? s2 : (cudaStream_t)0;

    if (streams_ok) {
        cudaEventRecord(evFork, (cudaStream_t)0);
        cudaStreamWaitEvent(side, evFork, 0);
    }

    // side stream: zero-fills + CSR build (independent of GEMM)
    zero_misc_kernel<<<dim3(N_NODES / 256, P_META), 256, 0, side>>>();
    if (atten_ptr)
        zero_atten_kernel<<<(N_NODES * (N_NODES / 4)) / 256, 256, 0, side>>>(
            (float4*)atten_ptr);
    hist_kernel<<<dim3(NE / 256, P_META), 256, 0, side>>>(edst);
    scan_kernel<<<P_META, 1024, 0, side>>>();
    csr_scatter_kernel<<<dim3(NE / 256, P_META), 256, 0, side>>>(esrc, edst);

    // main stream: GEMM + el/er
    gemm_feat_kernel<<<dim3(HD / 128, N_NODES / 128, P_META), 256>>>(h, fc);
    eler_kernel<<<dim3(N_NODES, P_META), 256>>>(al, ar);

    if (streams_ok) {
        cudaEventRecord(evJoin, side);
        cudaStreamWaitEvent((cudaStream_t)0, evJoin, 0);
    }

    gat_aggregate_kernel<<<dim3(N_NODES / 8, P_META), 256>>>(bias);

    sem_v_kernel<<<2, 256>>>(w1, w2, b1);
    sem_w_kernel<<<(N_NODES * P_META * 32) / 256, 256>>>();
    beta_kernel<<<1, 32>>>();
    combine_z_kernel<<<(N_NODES * HD / 4) / 256, 256>>>();
    if (out_ptr)
        out_kernel<<<N_NODES, 64>>>(pw, pb, out_ptr);
    if (atten_ptr)
        atten_scatter_kernel<<<dim3(NE / 256, P_META), 256>>>(esrc, edst, atten_ptr);
}